// round 3
// baseline (speedup 1.0000x reference)
#include <cuda_runtime.h>
#include <cstdint>
#include <cstddef>

// ---------------- scratch (device globals; no allocation allowed) ----------
// Only ONE 256MB scratch buffer; d_out doubles as the second scratch.
__device__ float g_b0[67108864];   // 256 MB
__device__ float g_wq_p1[4096];
__device__ float g_wq_f1[576];
__device__ float g_wq_p2[4096];
__device__ float g_wq_f2[576];
__device__ unsigned g_amax[4];     // bits of nonneg floats: max|x|, max|y1|, max|y2|, max|y3|

// ---------------- helpers --------------------------------------------------
__device__ __forceinline__ float warpMaxReduce(float v) {
#pragma unroll
    for (int o = 16; o; o >>= 1) v = fmaxf(v, __shfl_xor_sync(0xffffffffu, v, o));
    return v;
}

// valid result in thread 0; blockDim.x == 256
__device__ __forceinline__ float blockMax256(float v, float* sm) {
    v = warpMaxReduce(v);
    if ((threadIdx.x & 31) == 0) sm[threadIdx.x >> 5] = v;
    __syncthreads();
    if (threadIdx.x < 32) {
        v = (threadIdx.x < 8) ? sm[threadIdx.x] : 0.0f;
        v = warpMaxReduce(v);
    }
    return v;
}

__device__ __forceinline__ float quant(float x, float inv, float s, float qm) {
    float r = rintf(x * inv);
    r = fmaxf(-qm, fminf(qm, r));
    return r * s;
}

// ---------------- weight prep: quantize 4 weight tensors, zero amax --------
__global__ void wprep_kernel(const float* __restrict__ wp1, const float* __restrict__ wf1,
                             const float* __restrict__ wp2, const float* __restrict__ wf2) {
    __shared__ float sm[32];
    __shared__ float s_scale;
    int b = blockIdx.x;
    const float* src; float* dst; int n;
    if (b == 0)      { src = wp1; dst = g_wq_p1; n = 4096; }
    else if (b == 1) { src = wf1; dst = g_wq_f1; n = 576;  }
    else if (b == 2) { src = wp2; dst = g_wq_p2; n = 4096; }
    else             { src = wf2; dst = g_wq_f2; n = 576;  }
    if (b == 0 && threadIdx.x < 4) g_amax[threadIdx.x] = 0u;

    float m = 0.0f;
    for (int i = threadIdx.x; i < n; i += 256) m = fmaxf(m, fabsf(src[i]));
    m = blockMax256(m, sm);
    if (threadIdx.x == 0) s_scale = m / 7.0f + 1e-12f;   // W_BITS=4 -> qmax=7
    __syncthreads();
    float s = s_scale, inv = 1.0f / s;
    for (int i = threadIdx.x; i < n; i += 256) dst[i] = quant(src[i], inv, s, 7.0f);
}

// ---------------- pass A: max|x| -------------------------------------------
__global__ __launch_bounds__(256) void amax_kernel(const float4* __restrict__ x, int n4) {
    __shared__ float sm[32];
    float m = 0.0f;
    int stride = gridDim.x * blockDim.x;
    for (int i = blockIdx.x * blockDim.x + threadIdx.x; i < n4; i += stride) {
        float4 v = x[i];
        m = fmaxf(m, fmaxf(fmaxf(fabsf(v.x), fabsf(v.y)), fmaxf(fabsf(v.z), fabsf(v.w))));
    }
    m = blockMax256(m, sm);
    if (threadIdx.x == 0) atomicMax(&g_amax[0], __float_as_uint(m));
}

// ---------------- pointwise 1x1 conv (64->64), quant input, fused out-max --
// block = 256 threads: tx in [0,64) covers 4 spatial positions each (tile=256),
// ty in [0,4) covers 16 output channels each. f32x2 packed FMA, w duplicated.
__global__ __launch_bounds__(256) void pw_kernel(const float* __restrict__ src, float* __restrict__ dst,
                                                 const float* __restrict__ wq, int inIdx, int outIdx) {
    __shared__ float2 ws[4096];   // 32 KB: w duplicated into both f32x2 lanes
    __shared__ float  xs[4096];   // 16 KB: 16 ci x 256 positions, quantized
    const unsigned long long* wsu = reinterpret_cast<const unsigned long long*>(ws);

    int tid = threadIdx.x;
#pragma unroll
    for (int k = 0; k < 16; k++) {
        int i = k * 256 + tid;
        float w = wq[i];
        ws[i] = make_float2(w, w);
    }

    float s = __uint_as_float(g_amax[inIdx]) / 127.0f + 1e-12f;  // A_BITS=8 -> qmax=127
    float inv = 1.0f / s;

    int base = blockIdx.x << 8;     // 256 spatial positions per block (65536 per image, divides)
    int b = base >> 16;
    int hw = base & 65535;
    const float* sp = src + ((size_t)b << 22) + hw;   // + b*64*65536
    float*       dp = dst + ((size_t)b << 22) + hw;

    int tx = tid & 63, ty = tid >> 6;

    unsigned long long acc[16][2];
#pragma unroll
    for (int j = 0; j < 16; j++) { acc[j][0] = 0ull; acc[j][1] = 0ull; }

    for (int cc = 0; cc < 4; cc++) {
        __syncthreads();
#pragma unroll
        for (int k = 0; k < 16; k++)
            xs[k * 256 + tid] = quant(sp[(cc * 16 + k) * 65536 + tid], inv, s, 127.0f);
        __syncthreads();
#pragma unroll
        for (int cl = 0; cl < 16; cl++) {
            const unsigned long long* xp =
                reinterpret_cast<const unsigned long long*>(&xs[cl * 256 + tx * 4]);
            unsigned long long xlo = xp[0], xhi = xp[1];
            int wb = cc * 16 + cl;
#pragma unroll
            for (int j = 0; j < 16; j++) {
                unsigned long long w2 = wsu[(ty * 16 + j) * 64 + wb];
                asm("fma.rn.f32x2 %0, %1, %2, %0;" : "+l"(acc[j][0]) : "l"(xlo), "l"(w2));
                asm("fma.rn.f32x2 %0, %1, %2, %0;" : "+l"(acc[j][1]) : "l"(xhi), "l"(w2));
            }
        }
    }

    float lmax = 0.0f;
#pragma unroll
    for (int j = 0; j < 16; j++) {
        float4 o;
        asm("mov.b64 {%0,%1}, %2;" : "=f"(o.x), "=f"(o.y) : "l"(acc[j][0]));
        asm("mov.b64 {%0,%1}, %2;" : "=f"(o.z), "=f"(o.w) : "l"(acc[j][1]));
        lmax = fmaxf(lmax, fmaxf(fmaxf(fabsf(o.x), fabsf(o.y)), fmaxf(fabsf(o.z), fabsf(o.w))));
        int co = ty * 16 + j;
        *reinterpret_cast<float4*>(dp + co * 65536 + tx * 4) = o;
    }
    __syncthreads();               // done reading xs; reuse it for reduction
    float m = blockMax256(lmax, xs);
    if (tid == 0) atomicMax(&g_amax[outIdx], __float_as_uint(m));
}

// ---------------- depthwise 3x3 + PReLU (+ optional residual), quant input -
// block = 256 threads = one row width; each block does one (b,c, 8-row tile).
__global__ __launch_bounds__(256) void dw_kernel(const float* __restrict__ src, float* __restrict__ dst,
                                                 const float* __restrict__ wq, const float* __restrict__ alpha,
                                                 const float* __restrict__ res, int inIdx, int outIdx) {
    __shared__ float rows[10][256];
    __shared__ float sm[32];
    int tid = threadIdx.x;
    int blk = blockIdx.x;
    int ht = blk & 31;
    int c  = (blk >> 5) & 63;
    int b  = blk >> 11;
    size_t plane = ((size_t)(b * 64 + c)) << 16;
    const float* sp = src + plane;

    float s = __uint_as_float(g_amax[inIdx]) / 127.0f + 1e-12f;
    float inv = 1.0f / s;

    int h0 = ht << 3;
#pragma unroll
    for (int i = 0; i < 10; i++) {
        int gh = h0 - 1 + i;
        rows[i][tid] = (gh >= 0 && gh < 256) ? quant(sp[gh * 256 + tid], inv, s, 127.0f) : 0.0f;
    }
    __syncthreads();

    float w0 = wq[c*9+0], w1 = wq[c*9+1], w2 = wq[c*9+2];
    float w3 = wq[c*9+3], w4 = wq[c*9+4], w5 = wq[c*9+5];
    float w6 = wq[c*9+6], w7 = wq[c*9+7], w8 = wq[c*9+8];
    float a  = alpha[c];

    bool hasL = (tid > 0), hasR = (tid < 255);
    float lmax = 0.0f;
#pragma unroll
    for (int r = 0; r < 8; r++) {
        float v;
        v  = w0 * (hasL ? rows[r  ][tid-1] : 0.0f) + w1 * rows[r  ][tid] + w2 * (hasR ? rows[r  ][tid+1] : 0.0f);
        v += w3 * (hasL ? rows[r+1][tid-1] : 0.0f) + w4 * rows[r+1][tid] + w5 * (hasR ? rows[r+1][tid+1] : 0.0f);
        v += w6 * (hasL ? rows[r+2][tid-1] : 0.0f) + w7 * rows[r+2][tid] + w8 * (hasR ? rows[r+2][tid+1] : 0.0f);
        v = v > 0.0f ? v : a * v;       // PReLU
        lmax = fmaxf(lmax, fabsf(v));   // max BEFORE residual (matches qconv input)
        int off = (h0 + r) * 256 + tid;
        if (res) v += res[plane + off]; // final residual (pass E only)
        dst[plane + off] = v;
    }

    if (outIdx >= 0) {
        __syncthreads();
        float m = blockMax256(lmax, sm);
        if (tid == 0) atomicMax(&g_amax[outIdx], __float_as_uint(m));
    }
}

// ---------------- launch ----------------------------------------------------
extern "C" void kernel_launch(void* const* d_in, const int* in_sizes, int n_in,
                              void* d_out, int out_size) {
    const float* x   = (const float*)d_in[0];
    const float* wp1 = (const float*)d_in[1];
    const float* wf1 = (const float*)d_in[2];
    const float* wp2 = (const float*)d_in[3];
    const float* wf2 = (const float*)d_in[4];
    const float* a1  = (const float*)d_in[5];
    const float* a2  = (const float*)d_in[6];
    float* out = (float*)d_out;

    float *b0, *qp1, *qf1, *qp2, *qf2;
    cudaGetSymbolAddress((void**)&b0,  g_b0);
    cudaGetSymbolAddress((void**)&qp1, g_wq_p1);
    cudaGetSymbolAddress((void**)&qf1, g_wq_f1);
    cudaGetSymbolAddress((void**)&qp2, g_wq_p2);
    cudaGetSymbolAddress((void**)&qf2, g_wq_f2);

    // d_out doubles as scratch for y2; final pass fully overwrites it.
    wprep_kernel<<<4, 256>>>(wp1, wf1, wp2, wf2);              // quantize weights, zero amax
    amax_kernel<<<4096, 256>>>((const float4*)x, 16777216);    // max|x|
    pw_kernel<<<4096, 256>>>(x,   b0,  qp1, 0, 1);             // conv1x1 #1 -> b0, max|y1|
    dw_kernel<<<32768, 256>>>(b0, out, qf1, a1, nullptr, 1, 2);// dw3x3 #1 + prelu -> out, max|y2|
    pw_kernel<<<4096, 256>>>(out, b0,  qp2, 2, 3);             // conv1x1 #2 -> b0, max|y3|
    dw_kernel<<<32768, 256>>>(b0, out, qf2, a2, x, 3, -1);     // dw3x3 #2 + prelu + x -> out
}

// round 5
// speedup vs baseline: 1.8517x; 1.8517x over previous
#include <cuda_runtime.h>
#include <cstdint>
#include <cstddef>

// ---------------- scratch (device globals; no allocation allowed) ----------
__device__ float g_b0[67108864];   // 256 MB; d_out doubles as the second scratch
__device__ int   g_wqi_p1[1024];   // packed int8 weights [co][16 kwords]
__device__ int   g_wqi_p2[1024];
__device__ float g_wq_f1[576];     // quantized float dw weights
__device__ float g_wq_f2[576];
__device__ float g_wscale[2];      // weight scales for p1, p2
__device__ unsigned g_amax[4];     // bits of nonneg floats: max|x|,|y1|,|y2|,|y3|

// ---------------- helpers --------------------------------------------------
__device__ __forceinline__ float warpMaxReduce(float v) {
#pragma unroll
    for (int o = 16; o; o >>= 1) v = fmaxf(v, __shfl_xor_sync(0xffffffffu, v, o));
    return v;
}

// valid result in thread 0; blockDim.x == 256
__device__ __forceinline__ float blockMax256(float v, float* sm) {
    v = warpMaxReduce(v);
    if ((threadIdx.x & 31) == 0) sm[threadIdx.x >> 5] = v;
    __syncthreads();
    if (threadIdx.x < 32) {
        v = (threadIdx.x < 8) ? sm[threadIdx.x] : 0.0f;
        v = warpMaxReduce(v);
    }
    return v;
}

__device__ __forceinline__ float quant(float x, float inv, float s, float qm) {
    float r = rintf(x * inv);
    r = fmaxf(-qm, fminf(qm, r));
    return r * s;
}

__device__ __forceinline__ int qint8(float x, float inv, int qm) {
    int q = __float2int_rn(x * inv);
    return max(-qm, min(qm, q));
}

// ---------------- weight prep ----------------------------------------------
// b=0: p1 -> packed int8 + scale; b=1: f1 -> float; b=2: p2; b=3: f2.
__global__ void wprep_kernel(const float* __restrict__ wp1, const float* __restrict__ wf1,
                             const float* __restrict__ wp2, const float* __restrict__ wf2) {
    __shared__ float sm[32];
    __shared__ float s_scale;
    int b = blockIdx.x;
    const float* src = (b == 0) ? wp1 : (b == 1) ? wf1 : (b == 2) ? wp2 : wf2;
    int n = (b & 1) ? 576 : 4096;
    if (b == 0 && threadIdx.x < 4) g_amax[threadIdx.x] = 0u;

    float m = 0.0f;
    for (int i = threadIdx.x; i < n; i += 256) m = fmaxf(m, fabsf(src[i]));
    m = blockMax256(m, sm);
    if (threadIdx.x == 0) s_scale = m / 7.0f + 1e-12f;   // W_BITS=4 -> qmax=7
    __syncthreads();
    float s = s_scale, inv = 1.0f / s;

    if (b & 1) {  // depthwise: quantized float weights
        float* dst = (b == 1) ? g_wq_f1 : g_wq_f2;
        for (int i = threadIdx.x; i < n; i += 256) dst[i] = quant(src[i], inv, s, 7.0f);
    } else {      // pointwise: packed int8, [co][k] with k = 4 input channels
        int* dst = (b == 0) ? g_wqi_p1 : g_wqi_p2;
        if (threadIdx.x == 0) g_wscale[b >> 1] = s;
        for (int wi = threadIdx.x; wi < 1024; wi += 256) {
            int co = wi >> 4, k = wi & 15;
            int p = 0;
#pragma unroll
            for (int e = 0; e < 4; e++) {
                int q = qint8(src[co * 64 + 4 * k + e], inv, 7);
                p |= (q & 0xff) << (8 * e);
            }
            dst[wi] = p;
        }
    }
}

// ---------------- pass A: max|x| -------------------------------------------
__global__ __launch_bounds__(256) void amax_kernel(const float4* __restrict__ x, int n4) {
    __shared__ float sm[32];
    float m = 0.0f;
    int stride = gridDim.x * blockDim.x;
    for (int i = blockIdx.x * blockDim.x + threadIdx.x; i < n4; i += stride) {
        float4 v = x[i];
        m = fmaxf(m, fmaxf(fmaxf(fabsf(v.x), fabsf(v.y)), fmaxf(fabsf(v.z), fabsf(v.w))));
    }
    m = blockMax256(m, sm);
    if (threadIdx.x == 0) atomicMax(&g_amax[0], __float_as_uint(m));
}

// ---------------- pointwise 1x1 conv (64->64) via dp4a ---------------------
// block = 256 threads over 256 spatial positions. Stage: each thread quantizes
// all 64 channels of its position into 16 packed int8 words in smem.
// Compute: tx in [0,64) -> 4 positions, ty in [0,4) -> 16 output channels.
// x resident in 16 int4 regs; weights 4x int4 per output channel; exact int acc.
__global__ __launch_bounds__(256) void pw_kernel(const float* __restrict__ src, float* __restrict__ dst,
                                                 const int* __restrict__ wp, int inIdx, int outIdx,
                                                 int wsIdx) {
    __shared__ int ws[1024];       // [co][16]
    __shared__ int xs[16][256];    // [kword][pos]

    int tid = threadIdx.x;
#pragma unroll
    for (int q = 0; q < 4; q++) ws[q * 256 + tid] = wp[q * 256 + tid];

    float s = __uint_as_float(g_amax[inIdx]) / 127.0f + 1e-12f;  // A_BITS=8
    float inv = 1.0f / s;

    int base = blockIdx.x << 8;
    int b = base >> 16;
    int hw = base & 65535;
    const float* sp = src + ((size_t)b << 22) + hw;
    float*       dp = dst + ((size_t)b << 22) + hw;

    // stage all 64 channels of position `tid`, packed 4 channels per word
#pragma unroll
    for (int k = 0; k < 16; k++) {
        int p = 0;
#pragma unroll
        for (int e = 0; e < 4; e++) {
            int q = qint8(sp[(4 * k + e) * 65536 + tid], inv, 127);
            p |= (q & 0xff) << (8 * e);
        }
        xs[k][tid] = p;
    }
    __syncthreads();

    int tx = tid & 63, ty = tid >> 6;

    int4 xv[16];
#pragma unroll
    for (int k = 0; k < 16; k++) xv[k] = *reinterpret_cast<const int4*>(&xs[k][4 * tx]);

    float mult = s * g_wscale[wsIdx];
    float lmax = 0.0f;

#pragma unroll
    for (int j = 0; j < 16; j++) {
        int co = ty * 16 + j;
        const int4* wrow = reinterpret_cast<const int4*>(&ws[co * 16]);
        int a0 = 0, a1 = 0, a2 = 0, a3 = 0;
#pragma unroll
        for (int kq = 0; kq < 4; kq++) {
            int4 w4 = wrow[kq];
            a0 = __dp4a(xv[4*kq+0].x, w4.x, a0); a1 = __dp4a(xv[4*kq+0].y, w4.x, a1);
            a2 = __dp4a(xv[4*kq+0].z, w4.x, a2); a3 = __dp4a(xv[4*kq+0].w, w4.x, a3);
            a0 = __dp4a(xv[4*kq+1].x, w4.y, a0); a1 = __dp4a(xv[4*kq+1].y, w4.y, a1);
            a2 = __dp4a(xv[4*kq+1].z, w4.y, a2); a3 = __dp4a(xv[4*kq+1].w, w4.y, a3);
            a0 = __dp4a(xv[4*kq+2].x, w4.z, a0); a1 = __dp4a(xv[4*kq+2].y, w4.z, a1);
            a2 = __dp4a(xv[4*kq+2].z, w4.z, a2); a3 = __dp4a(xv[4*kq+2].w, w4.z, a3);
            a0 = __dp4a(xv[4*kq+3].x, w4.w, a0); a1 = __dp4a(xv[4*kq+3].y, w4.w, a1);
            a2 = __dp4a(xv[4*kq+3].z, w4.w, a2); a3 = __dp4a(xv[4*kq+3].w, w4.w, a3);
        }
        float4 o;
        o.x = __int2float_rn(a0) * mult;
        o.y = __int2float_rn(a1) * mult;
        o.z = __int2float_rn(a2) * mult;
        o.w = __int2float_rn(a3) * mult;
        lmax = fmaxf(lmax, fmaxf(fmaxf(fabsf(o.x), fabsf(o.y)), fmaxf(fabsf(o.z), fabsf(o.w))));
        *reinterpret_cast<float4*>(dp + co * 65536 + 4 * tx) = o;
    }
    __syncthreads();               // xs reads done; reuse for reduction
    float m = blockMax256(lmax, reinterpret_cast<float*>(xs));
    if (tid == 0) atomicMax(&g_amax[outIdx], __float_as_uint(m));
}

// ---------------- depthwise 3x3 + PReLU (+ optional residual) --------------
// block = 256 threads covering 32 rows x 256 cols of one (b,c) plane.
// tx in [0,64) -> 4 consecutive cols, ty in [0,4) -> 8 rows, register
// sliding window of 3 x 6 floats.
__global__ __launch_bounds__(256) void dw_kernel(const float* __restrict__ src, float* __restrict__ dst,
                                                 const float* __restrict__ wq, const float* __restrict__ alpha,
                                                 const float* __restrict__ res, int inIdx, int outIdx) {
    __shared__ float rows[34][256];
    __shared__ float sm[32];
    int tid = threadIdx.x;
    int blk = blockIdx.x;
    int seg = blk & 7;
    int bc  = blk >> 3;
    int c   = bc & 63;
    int b   = bc >> 6;
    size_t plane = ((size_t)(b * 64 + c)) << 16;
    const float* sp = src + plane;
    int H0 = seg << 5;

    float s = __uint_as_float(g_amax[inIdx]) / 127.0f + 1e-12f;
    float inv = 1.0f / s;

#pragma unroll
    for (int i = 0; i < 34; i++) {
        int gh = H0 - 1 + i;
        rows[i][tid] = (gh >= 0 && gh < 256) ? quant(sp[gh * 256 + tid], inv, s, 127.0f) : 0.0f;
    }
    __syncthreads();

    float w0 = wq[c*9+0], w1 = wq[c*9+1], w2 = wq[c*9+2];
    float w3 = wq[c*9+3], w4 = wq[c*9+4], w5 = wq[c*9+5];
    float w6 = wq[c*9+6], w7 = wq[c*9+7], w8 = wq[c*9+8];
    float a  = alpha[c];

    int tx = tid & 63, ty = tid >> 6;
    int c0 = tx * 4;
    int jb = ty * 8;   // local output rows jb..jb+7 use rows[jb..jb+9]

    float f0[6], f1[6], f2[6];
    // load line l into f
    #define LOADLINE(l, f) do {                                         \
        float4 _v = *reinterpret_cast<const float4*>(&rows[(l)][c0]);   \
        (f)[1] = _v.x; (f)[2] = _v.y; (f)[3] = _v.z; (f)[4] = _v.w;     \
        (f)[0] = (tx > 0)  ? rows[(l)][c0 - 1] : 0.0f;                  \
        (f)[5] = (tx < 63) ? rows[(l)][c0 + 4] : 0.0f;                  \
    } while (0)

    LOADLINE(jb + 0, f0);
    LOADLINE(jb + 1, f1);

    float lmax = 0.0f;
#pragma unroll
    for (int rr = 0; rr < 8; rr++) {
        LOADLINE(jb + rr + 2, f2);
        int grow = H0 + jb + rr;
        size_t off = plane + (size_t)grow * 256 + c0;
        float4 o;
        float* op = &o.x;
#pragma unroll
        for (int e = 0; e < 4; e++) {
            float v;
            v  = w0 * f0[e] + w1 * f0[e+1] + w2 * f0[e+2];
            v += w3 * f1[e] + w4 * f1[e+1] + w5 * f1[e+2];
            v += w6 * f2[e] + w7 * f2[e+1] + w8 * f2[e+2];
            v = v > 0.0f ? v : a * v;          // PReLU
            lmax = fmaxf(lmax, fabsf(v));      // max BEFORE residual
            op[e] = v;
        }
        if (res) {
            float4 r4 = *reinterpret_cast<const float4*>(res + off);
            o.x += r4.x; o.y += r4.y; o.z += r4.z; o.w += r4.w;
        }
        *reinterpret_cast<float4*>(dst + off) = o;
#pragma unroll
        for (int e = 0; e < 6; e++) { f0[e] = f1[e]; f1[e] = f2[e]; }
    }
    #undef LOADLINE

    if (outIdx >= 0) {
        __syncthreads();
        float m = blockMax256(lmax, sm);
        if (tid == 0) atomicMax(&g_amax[outIdx], __float_as_uint(m));
    }
}

// ---------------- launch ----------------------------------------------------
extern "C" void kernel_launch(void* const* d_in, const int* in_sizes, int n_in,
                              void* d_out, int out_size) {
    const float* x   = (const float*)d_in[0];
    const float* wp1 = (const float*)d_in[1];
    const float* wf1 = (const float*)d_in[2];
    const float* wp2 = (const float*)d_in[3];
    const float* wf2 = (const float*)d_in[4];
    const float* a1  = (const float*)d_in[5];
    const float* a2  = (const float*)d_in[6];
    float* out = (float*)d_out;

    float *b0, *qf1, *qf2;
    int *qi1, *qi2;
    cudaGetSymbolAddress((void**)&b0,  g_b0);
    cudaGetSymbolAddress((void**)&qi1, g_wqi_p1);
    cudaGetSymbolAddress((void**)&qi2, g_wqi_p2);
    cudaGetSymbolAddress((void**)&qf1, g_wq_f1);
    cudaGetSymbolAddress((void**)&qf2, g_wq_f2);

    // d_out doubles as scratch for y2; final pass fully overwrites it.
    wprep_kernel<<<4, 256>>>(wp1, wf1, wp2, wf2);               // weights + zero amax
    amax_kernel<<<4096, 256>>>((const float4*)x, 16777216);     // max|x|
    pw_kernel<<<4096, 256>>>(x,   b0,  qi1, 0, 1, 0);           // conv1x1 #1 -> b0
    dw_kernel<<<8192, 256>>>(b0,  out, qf1, a1, nullptr, 1, 2); // dw3x3 #1 + prelu -> out
    pw_kernel<<<4096, 256>>>(out, b0,  qi2, 2, 3, 1);           // conv1x1 #2 -> b0
    dw_kernel<<<8192, 256>>>(b0,  out, qf2, a2, x, 3, -1);      // dw3x3 #2 + prelu + x -> out
}

// round 6
// speedup vs baseline: 2.0836x; 1.1252x over previous
#include <cuda_runtime.h>
#include <cstdint>
#include <cstddef>

// ---------------- scratch (device globals; no allocation allowed) ----------
__device__ short g_s0[67108864];   // 128 MB int16 accumulator ping
__device__ short g_s1[67108864];   // 128 MB int16 accumulator pong
__device__ int   g_wqi[2][1024];   // packed int8 pw weights [p1|p2][co][16 kwords]
__device__ float g_wqf[2][576];    // integer-valued dw weights (no scale) [f1|f2]
__device__ float g_wscale[4];      // s_wp1, s_wf1, s_wp2, s_wf2
__device__ unsigned g_amax[4];     // bits of nonneg floats: max|x|,|y1|,|y2|,|y3|

// ---------------- helpers --------------------------------------------------
__device__ __forceinline__ float warpMaxReduce(float v) {
#pragma unroll
    for (int o = 16; o; o >>= 1) v = fmaxf(v, __shfl_xor_sync(0xffffffffu, v, o));
    return v;
}

// valid result in thread 0; blockDim.x == 256
__device__ __forceinline__ float blockMax256(float v, float* sm) {
    v = warpMaxReduce(v);
    if ((threadIdx.x & 31) == 0) sm[threadIdx.x >> 5] = v;
    __syncthreads();
    if (threadIdx.x < 32) {
        v = (threadIdx.x < 8) ? sm[threadIdx.x] : 0.0f;
        v = warpMaxReduce(v);
    }
    return v;
}

// ---------------- weight prep ----------------------------------------------
// b=0: p1 -> packed int8; b=1: f1 -> int-valued float; b=2: p2; b=3: f2.
// |w|/s < qmax is guaranteed by s = max/qmax + 1e-12, so no clamp needed.
__global__ void wprep_kernel(const float* __restrict__ wp1, const float* __restrict__ wf1,
                             const float* __restrict__ wp2, const float* __restrict__ wf2) {
    __shared__ float sm[32];
    __shared__ float s_sh;
    int b = blockIdx.x;
    const float* src = (b == 0) ? wp1 : (b == 1) ? wf1 : (b == 2) ? wp2 : wf2;
    int n = (b & 1) ? 576 : 4096;
    if (b == 0 && threadIdx.x < 4) g_amax[threadIdx.x] = 0u;

    float m = 0.0f;
    for (int i = threadIdx.x; i < n; i += 256) m = fmaxf(m, fabsf(src[i]));
    m = blockMax256(m, sm);
    if (threadIdx.x == 0) { s_sh = m / 7.0f + 1e-12f; g_wscale[b] = s_sh; }
    __syncthreads();
    float inv = 1.0f / s_sh;

    if (b & 1) {  // depthwise: integer-valued float weights
        float* dst = g_wqf[b >> 1];
        for (int i = threadIdx.x; i < n; i += 256) dst[i] = rintf(src[i] * inv);
    } else {      // pointwise: packed int8, [co][kword], kword = 4 input channels
        int* dst = g_wqi[b >> 1];
        for (int wi = threadIdx.x; wi < 1024; wi += 256) {
            int co = wi >> 4, k = wi & 15;
            int p = 0;
#pragma unroll
            for (int e = 0; e < 4; e++) {
                int q = __float2int_rn(src[co * 64 + 4 * k + e] * inv);
                p |= (q & 0xff) << (8 * e);
            }
            dst[wi] = p;
        }
    }
}

// ---------------- pass A: max|x| -------------------------------------------
__global__ __launch_bounds__(256) void amax_kernel(const float4* __restrict__ x, int n4) {
    __shared__ float sm[32];
    float m = 0.0f;
    int stride = gridDim.x * blockDim.x;
    for (int i = blockIdx.x * blockDim.x + threadIdx.x; i < n4; i += stride) {
        float4 v = x[i];
        m = fmaxf(m, fmaxf(fmaxf(fabsf(v.x), fabsf(v.y)), fmaxf(fabsf(v.z), fabsf(v.w))));
    }
    m = blockMax256(m, sm);
    if (threadIdx.x == 0) atomicMax(&g_amax[0], __float_as_uint(m));
}

// ---------------- pointwise 1x1 conv (64->64) via dp4a ---------------------
// MODE 0: input fp32 x (pw1).  MODE 1: input int16 dw-acc + PReLU (pw2).
// Output: int16 accumulators; fused amax of |acc|*mult_out.
template<int MODE>
__global__ __launch_bounds__(256) void pw_kernel(const float* __restrict__ srcf,
                                                 const short* __restrict__ srch,
                                                 short* __restrict__ dst,
                                                 const float* __restrict__ alpha) {
    __shared__ int ws[1024];       // [co][16]
    __shared__ int xs[16][256];    // [kword][pos]
    __shared__ float nf_s[64];     // per-channel negative-branch factor (MODE 1)
    __shared__ float smr[32];

    int tid = threadIdx.x;
    const int* wp = (MODE == 0) ? g_wqi[0] : g_wqi[1];
#pragma unroll
    for (int q = 0; q < 4; q++) ws[q * 256 + tid] = wp[q * 256 + tid];

    float pf, mult_out;
    if (MODE == 0) {
        float s = __uint_as_float(g_amax[0]) / 127.0f + 1e-12f;
        pf = 1.0f / s;
        mult_out = s * g_wscale[0];
    } else {
        float s1 = __uint_as_float(g_amax[1]) / 127.0f + 1e-12f;
        float s2 = __uint_as_float(g_amax[2]) / 127.0f + 1e-12f;
        float u = s1 * g_wscale[1];           // value = acc_dw * u (pre-PReLU)
        pf = u / s2;                          // positive branch: quantize directly
        if (tid < 64) nf_s[tid] = alpha[tid] * pf;  // negative branch folds alpha
        mult_out = s2 * g_wscale[2];
    }
    if (MODE == 1) __syncthreads();

    int base = blockIdx.x << 8;               // 256 spatial positions per block
    size_t ofs = ((size_t)(base >> 16) << 22) + (size_t)(base & 65535);

    // stage all 64 channels of position `tid`, packed 4 channels per word
#pragma unroll
    for (int k = 0; k < 16; k++) {
        int p = 0;
#pragma unroll
        for (int e = 0; e < 4; e++) {
            int q;
            if (MODE == 0) {
                q = __float2int_rn(srcf[ofs + (4 * k + e) * 65536 + tid] * pf);
            } else {
                float v = (float)srch[ofs + (4 * k + e) * 65536 + tid];
                float f = (v < 0.0f) ? nf_s[4 * k + e] : pf;
                q = __float2int_rn(v * f);
            }
            q = max(-127, min(127, q));       // guard ulp edge before int8 pack
            p |= (q & 0xff) << (8 * e);
        }
        xs[k][tid] = p;
    }
    __syncthreads();

    int tx = tid & 63, ty = tid >> 6;

    int4 xv[16];
#pragma unroll
    for (int k = 0; k < 16; k++) xv[k] = *reinterpret_cast<const int4*>(&xs[k][4 * tx]);

    int lm = 0;
    short* dp = dst + ofs;
#pragma unroll
    for (int j = 0; j < 16; j++) {
        int co = ty * 16 + j;
        const int4* wrow = reinterpret_cast<const int4*>(&ws[co * 16]);
        int a0 = 0, a1 = 0, a2 = 0, a3 = 0;
#pragma unroll
        for (int kq = 0; kq < 4; kq++) {
            int4 w4 = wrow[kq];
            a0 = __dp4a(xv[4*kq+0].x, w4.x, a0); a1 = __dp4a(xv[4*kq+0].y, w4.x, a1);
            a2 = __dp4a(xv[4*kq+0].z, w4.x, a2); a3 = __dp4a(xv[4*kq+0].w, w4.x, a3);
            a0 = __dp4a(xv[4*kq+1].x, w4.y, a0); a1 = __dp4a(xv[4*kq+1].y, w4.y, a1);
            a2 = __dp4a(xv[4*kq+1].z, w4.y, a2); a3 = __dp4a(xv[4*kq+1].w, w4.y, a3);
            a0 = __dp4a(xv[4*kq+2].x, w4.z, a0); a1 = __dp4a(xv[4*kq+2].y, w4.z, a1);
            a2 = __dp4a(xv[4*kq+2].z, w4.z, a2); a3 = __dp4a(xv[4*kq+2].w, w4.z, a3);
            a0 = __dp4a(xv[4*kq+3].x, w4.w, a0); a1 = __dp4a(xv[4*kq+3].y, w4.w, a1);
            a2 = __dp4a(xv[4*kq+3].z, w4.w, a2); a3 = __dp4a(xv[4*kq+3].w, w4.w, a3);
        }
        lm = max(lm, max(max(abs(a0), abs(a1)), max(abs(a2), abs(a3))));
        short4 o = make_short4((short)a0, (short)a1, (short)a2, (short)a3);
        *reinterpret_cast<short4*>(dp + co * 65536 + 4 * tx) = o;
    }
    float m = blockMax256((float)lm * mult_out, smr);
    if (tid == 0) atomicMax(&g_amax[(MODE == 0) ? 1 : 3], __float_as_uint(m));
}

// ---------------- depthwise 3x3 ---------------------------------------------
// MODE 0 (dw1): int16 in -> int16 pre-PReLU acc out; amax over PReLU'd value.
// MODE 1 (dw2): int16 in -> PReLU + residual -> fp32 out.
template<int MODE>
__global__ __launch_bounds__(256) void dw_kernel(const short* __restrict__ src,
                                                 short* __restrict__ dsth,
                                                 float* __restrict__ dstf,
                                                 const float* __restrict__ alpha,
                                                 const float* __restrict__ res) {
    __shared__ float rows[34][256];
    __shared__ float smr[32];
    int tid = threadIdx.x;
    int blk = blockIdx.x;
    int seg = blk & 7;
    int bc  = blk >> 3;
    int c   = bc & 63;
    int b   = bc >> 6;
    size_t plane = ((size_t)(b * 64 + c)) << 16;
    int H0 = seg << 5;

    const float* wq = (MODE == 0) ? g_wqf[0] : g_wqf[1];
    float f_in, u_out;
    if (MODE == 0) {
        float s0 = __uint_as_float(g_amax[0]) / 127.0f + 1e-12f;
        float s1 = __uint_as_float(g_amax[1]) / 127.0f + 1e-12f;
        f_in  = s0 * g_wscale[0] / s1;    // int16 acc -> quant units of s1
        u_out = s1 * g_wscale[1];
    } else {
        float s2 = __uint_as_float(g_amax[2]) / 127.0f + 1e-12f;
        float s3 = __uint_as_float(g_amax[3]) / 127.0f + 1e-12f;
        f_in  = s2 * g_wscale[2] / s3;
        u_out = s3 * g_wscale[3];
    }

    const short* sp = src + plane;
#pragma unroll
    for (int i = 0; i < 34; i++) {
        int gh = H0 - 1 + i;
        rows[i][tid] = (gh >= 0 && gh < 256)
                     ? rintf((float)sp[gh * 256 + tid] * f_in) : 0.0f;
    }
    __syncthreads();

    float w0 = wq[c*9+0], w1 = wq[c*9+1], w2 = wq[c*9+2];
    float w3 = wq[c*9+3], w4 = wq[c*9+4], w5 = wq[c*9+5];
    float w6 = wq[c*9+6], w7 = wq[c*9+7], w8 = wq[c*9+8];
    float a  = alpha[c];

    int tx = tid & 63, ty = tid >> 6;
    int c0 = tx * 4;
    int jb = ty * 8;

    float f0[6], f1[6], f2[6];
    #define LOADLINE(l, f) do {                                         \
        float4 _v = *reinterpret_cast<const float4*>(&rows[(l)][c0]);   \
        (f)[1] = _v.x; (f)[2] = _v.y; (f)[3] = _v.z; (f)[4] = _v.w;     \
        (f)[0] = (tx > 0)  ? rows[(l)][c0 - 1] : 0.0f;                  \
        (f)[5] = (tx < 63) ? rows[(l)][c0 + 4] : 0.0f;                  \
    } while (0)

    LOADLINE(jb + 0, f0);
    LOADLINE(jb + 1, f1);

    float lmax = 0.0f;
#pragma unroll
    for (int rr = 0; rr < 8; rr++) {
        LOADLINE(jb + rr + 2, f2);
        int grow = H0 + jb + rr;
        size_t off = plane + (size_t)grow * 256 + c0;
        float acc[4];
#pragma unroll
        for (int e = 0; e < 4; e++) {
            float v;
            v  = w0 * f0[e] + w1 * f0[e+1] + w2 * f0[e+2];
            v += w3 * f1[e] + w4 * f1[e+1] + w5 * f1[e+2];
            v += w6 * f2[e] + w7 * f2[e+1] + w8 * f2[e+2];
            acc[e] = v;                           // exact integer-valued
        }
        if (MODE == 0) {
            short4 o;
#pragma unroll
            for (int e = 0; e < 4; e++) {
                float y = acc[e] * u_out;
                y = y > 0.0f ? y : a * y;         // PReLU (for amax only)
                lmax = fmaxf(lmax, fabsf(y));
            }
            o.x = (short)__float2int_rn(acc[0]);
            o.y = (short)__float2int_rn(acc[1]);
            o.z = (short)__float2int_rn(acc[2]);
            o.w = (short)__float2int_rn(acc[3]);
            *reinterpret_cast<short4*>(dsth + off) = o;
        } else {
            float4 r4 = *reinterpret_cast<const float4*>(res + off);
            float4 o;
            float* op = &o.x;
            const float* rp = &r4.x;
#pragma unroll
            for (int e = 0; e < 4; e++) {
                float y = acc[e] * u_out;
                y = y > 0.0f ? y : a * y;         // PReLU
                op[e] = y + rp[e];                // residual
            }
            *reinterpret_cast<float4*>(dstf + off) = o;
        }
#pragma unroll
        for (int e = 0; e < 6; e++) { f0[e] = f1[e]; f1[e] = f2[e]; }
    }
    #undef LOADLINE

    if (MODE == 0) {
        float m = blockMax256(lmax, smr);
        if (tid == 0) atomicMax(&g_amax[2], __float_as_uint(m));
    }
}

// ---------------- launch ----------------------------------------------------
extern "C" void kernel_launch(void* const* d_in, const int* in_sizes, int n_in,
                              void* d_out, int out_size) {
    const float* x   = (const float*)d_in[0];
    const float* wp1 = (const float*)d_in[1];
    const float* wf1 = (const float*)d_in[2];
    const float* wp2 = (const float*)d_in[3];
    const float* wf2 = (const float*)d_in[4];
    const float* a1  = (const float*)d_in[5];
    const float* a2  = (const float*)d_in[6];
    float* out = (float*)d_out;

    short *s0, *s1;
    cudaGetSymbolAddress((void**)&s0, g_s0);
    cudaGetSymbolAddress((void**)&s1, g_s1);

    wprep_kernel<<<4, 256>>>(wp1, wf1, wp2, wf2);             // weights + zero amax
    amax_kernel<<<4096, 256>>>((const float4*)x, 16777216);   // max|x|
    pw_kernel<0><<<4096, 256>>>(x, nullptr, s0, nullptr);     // pw1 -> int16 acc, amax|y1|
    dw_kernel<0><<<8192, 256>>>(s0, s1, nullptr, a1, nullptr);// dw1 -> int16 acc, amax|y2|
    pw_kernel<1><<<4096, 256>>>(nullptr, s1, s0, a1);         // prelu+pw2 -> int16 acc, amax|y3|
    dw_kernel<1><<<8192, 256>>>(s0, nullptr, out, a2, x);     // dw2 + prelu + residual -> out
}